// round 10
// baseline (speedup 1.0000x reference)
#include <cuda_runtime.h>
#include <cstdint>

// PointConv: B=32, C=64, H=W=64, KH=KW=2 -> L=1024, n=256.
// Per l: D[p, b] = sum_k W[l][k][p] * patch[b][k] + bias[p, l]
// fp32 via 3-term bf16 split on mma.sync.m16n8k16. 2 CTAs/SM.
// R10: L2 prefetch 2 stages beyond TMA ring + 4-way split stage bulks.

#define HH 64
#define CC 64
#define NN 256
#define LL 1024

#define KSTAGE 16
#define NSTG   16
#define W_STAGE_BYTES (KSTAGE * NN * 4)       // 16384
#define BULK_SPLIT 4
#define BULK_BYTES (W_STAGE_BYTES / BULK_SPLIT)   // 4096
#define NWBUF  3
#define PF_AHEAD (NWBUF + 2)                   // prefetch distance (stages)

#define AROW  512                              // 256 p x bf16, XOR-swizzled
#define ATILE (KSTAGE * AROW)                  // 8192 (one of hi/mid)
#define ABUF  (2 * ATILE)                      // 16384 (hi + mid)

#define OFF_W0   0                             // 3 x 16384 = 49152
#define OFF_A    49152                         // 2 x 16384 = 32768
#define OFF_PH   81920                         // 32 x 512 = 16384
#define OFF_PM   98304                         // 16384
#define OFF_CTRL 114688
#define SMEM_TOTAL 114752

typedef unsigned long long u64;

__device__ __forceinline__ uint32_t swz(uint32_t row, uint32_t cb) {
    return row * AROW + (cb ^ ((row & 7) << 4));
}
__device__ __forceinline__ uint32_t cvt2(float lo, float hi) {  // pack {lo=low16, hi=high16}
    uint32_t r;
    asm("cvt.rn.bf16x2.f32 %0, %1, %2;" : "=r"(r) : "f"(hi), "f"(lo));
    return r;
}
__device__ __forceinline__ float lo_f(uint32_t p) { return __uint_as_float(p << 16); }
__device__ __forceinline__ float hi_f(uint32_t p) { return __uint_as_float(p & 0xffff0000u); }

__device__ __forceinline__ void mbar_init(uint32_t mbar, uint32_t count) {
    asm volatile("mbarrier.init.shared::cta.b64 [%0], %1;" :: "r"(mbar), "r"(count) : "memory");
}
__device__ __forceinline__ void mbar_expect_tx(uint32_t mbar, uint32_t bytes) {
    asm volatile("mbarrier.arrive.expect_tx.shared::cta.b64 _, [%0], %1;"
                 :: "r"(mbar), "r"(bytes) : "memory");
}
__device__ __forceinline__ void bulk_g2s(uint32_t dst, const void* src, uint32_t bytes, uint32_t mbar) {
    asm volatile("cp.async.bulk.shared::cta.global.mbarrier::complete_tx::bytes [%0], [%1], %2, [%3];"
                 :: "r"(dst), "l"(src), "r"(bytes), "r"(mbar) : "memory");
}
__device__ __forceinline__ void bulk_prefetch_l2(const void* src, uint32_t bytes) {
    asm volatile("cp.async.bulk.prefetch.L2.global [%0], %1;"
                 :: "l"(src), "r"(bytes) : "memory");
}
__device__ __forceinline__ void mbar_wait(uint32_t mbar, uint32_t parity) {
    asm volatile(
        "{\n\t.reg .pred P1;\n\t"
        "WAIT_LOOP_%=:\n\t"
        "mbarrier.try_wait.parity.shared::cta.b64 P1, [%0], %1, 0x989680;\n\t"
        "@P1 bra.uni WAIT_DONE_%=;\n\t"
        "bra.uni WAIT_LOOP_%=;\n\t"
        "WAIT_DONE_%=:\n\t}"
        :: "r"(mbar), "r"(parity) : "memory");
}
__device__ __forceinline__ void ldsm4t(uint32_t& r0, uint32_t& r1, uint32_t& r2, uint32_t& r3,
                                       uint32_t addr) {
    asm volatile("ldmatrix.sync.aligned.m8n8.x4.trans.shared.b16 {%0,%1,%2,%3}, [%4];"
                 : "=r"(r0), "=r"(r1), "=r"(r2), "=r"(r3) : "r"(addr));
}
__device__ __forceinline__ void mma_bf16(float* d, const uint32_t* a, const uint32_t* b) {
    asm volatile(
        "mma.sync.aligned.m16n8k16.row.col.f32.bf16.bf16.f32 "
        "{%0,%1,%2,%3}, {%4,%5,%6,%7}, {%8,%9}, {%0,%1,%2,%3};"
        : "+f"(d[0]), "+f"(d[1]), "+f"(d[2]), "+f"(d[3])
        : "r"(a[0]), "r"(a[1]), "r"(a[2]), "r"(a[3]), "r"(b[0]), "r"(b[1]));
}

__global__ void __launch_bounds__(256, 2)
pointconv_mma(const float* __restrict__ x,
              const float* __restrict__ w,
              const float* __restrict__ bias,
              float* __restrict__ out)
{
    extern __shared__ char smem[];
    const uint32_t sbase = (uint32_t)__cvta_generic_to_shared(smem);
    const int tid  = threadIdx.x;
    const int wid  = tid >> 5;
    const int lane = tid & 31;
    const int l  = blockIdx.x;
    const int ph = l >> 5, pw = l & 31;
    const float* __restrict__ wl = w + (size_t)l * (NN * NN);

    // ---- mbarriers + prefetch pipeline bootstrap ----
    if (tid == 0) {
        #pragma unroll
        for (int i = 0; i < NWBUF; i++) mbar_init(sbase + OFF_CTRL + i * 8, 1);
        asm volatile("fence.proxy.async.shared::cta;" ::: "memory");
        // L2 prefetch for stages [NWBUF, PF_AHEAD)
        #pragma unroll
        for (int s = NWBUF; s < PF_AHEAD; s++)
            bulk_prefetch_l2(wl + s * (KSTAGE * NN), W_STAGE_BYTES);
        // TMA ring: first NWBUF stages, each split into 4 bulks
        #pragma unroll
        for (int s = 0; s < NWBUF; s++) {
            uint32_t mb = sbase + OFF_CTRL + s * 8;
            mbar_expect_tx(mb, W_STAGE_BYTES);
            #pragma unroll
            for (int i = 0; i < BULK_SPLIT; i++)
                bulk_g2s(sbase + OFF_W0 + s * W_STAGE_BYTES + i * BULK_BYTES,
                         wl + s * (KSTAGE * NN) + i * (BULK_BYTES / 4),
                         BULK_BYTES, mb);
        }
    }

    // ---- patch gather + bf16 hi/mid split -> [b][k] swizzled ----
    {
        const int b  = tid & 31;
        const int cg = tid >> 5;
        #pragma unroll
        for (int ci = 0; ci < 8; ci++) {
            const int c = cg * 8 + ci;
            #pragma unroll
            for (int kh = 0; kh < 2; kh++) {
                const float2 v = *reinterpret_cast<const float2*>(
                    x + (size_t)(((b * CC + c) * HH + 2 * ph + kh) * HH + 2 * pw));
                const int k = c * 4 + kh * 2;
                const uint32_t hp = cvt2(v.x, v.y);
                const uint32_t mp = cvt2(v.x - lo_f(hp), v.y - hi_f(hp));
                const uint32_t a = swz((uint32_t)b, (uint32_t)(k * 2));
                *reinterpret_cast<uint32_t*>(smem + OFF_PH + a) = hp;
                *reinterpret_cast<uint32_t*>(smem + OFF_PM + a) = mp;
            }
        }
    }

    float d[2][4][4];
    #pragma unroll
    for (int i = 0; i < 2; i++)
        #pragma unroll
        for (int j = 0; j < 4; j++)
            #pragma unroll
            for (int r = 0; r < 4; r++) d[i][j][r] = 0.0f;

    const int wbase = wid * 32;
    const int bq = lane >> 2;
    const int kq = (lane & 3) * 2;
    const int lm_m = lane >> 3, lm_r = lane & 7;

    // ---- mainloop over 16 k-stages, 3-deep TMA ring + L2 prefetch ----
    #pragma unroll 1
    for (int s = 0; s < NSTG; s++) {
        const int wb = s % NWBUF;
        mbar_wait(sbase + OFF_CTRL + wb * 8, (s / NWBUF) & 1);

        const float* wbuf = reinterpret_cast<const float*>(smem + OFF_W0 + wb * W_STAGE_BYTES);
        char* A = smem + OFF_A + (s & 1) * ABUF;            // hi at A, mid at A+ATILE

        // convert: warp handles rows {wid, wid+8}
        #pragma unroll
        for (int j = 0; j < 2; j++) {
            const int r = wid + j * 8;
            const float4 va = *reinterpret_cast<const float4*>(wbuf + r * NN + lane * 4);
            const float4 vb = *reinterpret_cast<const float4*>(wbuf + r * NN + 128 + lane * 4);
            const uint32_t ha0 = cvt2(va.x, va.y), ha1 = cvt2(va.z, va.w);
            const uint32_t hb0 = cvt2(vb.x, vb.y), hb1 = cvt2(vb.z, vb.w);
            const uint32_t ma0 = cvt2(va.x - lo_f(ha0), va.y - hi_f(ha0));
            const uint32_t ma1 = cvt2(va.z - lo_f(ha1), va.w - hi_f(ha1));
            const uint32_t mb0 = cvt2(vb.x - lo_f(hb0), vb.y - hi_f(hb0));
            const uint32_t mb1 = cvt2(vb.z - lo_f(hb1), vb.w - hi_f(hb1));
            const uint32_t a0 = swz((uint32_t)r, (uint32_t)(lane * 8));
            const uint32_t a1 = swz((uint32_t)r, (uint32_t)(256 + lane * 8));
            *reinterpret_cast<uint2*>(A + a0)         = make_uint2(ha0, ha1);
            *reinterpret_cast<uint2*>(A + a1)         = make_uint2(hb0, hb1);
            *reinterpret_cast<uint2*>(A + ATILE + a0) = make_uint2(ma0, ma1);
            *reinterpret_cast<uint2*>(A + ATILE + a1) = make_uint2(mb0, mb1);
        }
        __syncthreads();

        if (tid == 0) {
            if (s + PF_AHEAD < NSTG)
                bulk_prefetch_l2(wl + (s + PF_AHEAD) * (KSTAGE * NN), W_STAGE_BYTES);
            if (s + NWBUF < NSTG) {
                uint32_t mb = sbase + OFF_CTRL + wb * 8;
                mbar_expect_tx(mb, W_STAGE_BYTES);
                #pragma unroll
                for (int i = 0; i < BULK_SPLIT; i++)
                    bulk_g2s(sbase + OFF_W0 + wb * W_STAGE_BYTES + i * BULK_BYTES,
                             wl + (s + NWBUF) * (KSTAGE * NN) + i * (BULK_BYTES / 4),
                             BULK_BYTES, mb);
            }
        }

        // B fragments for this stage's k16 chunk
        const int kg = s * KSTAGE;
        uint32_t bh[4][2], bm[4][2];
        #pragma unroll
        for (int nt = 0; nt < 4; nt++) {
            const uint32_t row = (uint32_t)(nt * 8 + bq);
            const uint32_t o0 = swz(row, (uint32_t)((kg + kq) * 2));
            const uint32_t o1 = swz(row, (uint32_t)((kg + kq) * 2 + 16));
            bh[nt][0] = *reinterpret_cast<uint32_t*>(smem + OFF_PH + o0);
            bh[nt][1] = *reinterpret_cast<uint32_t*>(smem + OFF_PH + o1);
            bm[nt][0] = *reinterpret_cast<uint32_t*>(smem + OFF_PM + o0);
            bm[nt][1] = *reinterpret_cast<uint32_t*>(smem + OFF_PM + o1);
        }

        const uint32_t Asm = sbase + OFF_A + (s & 1) * ABUF;
        #pragma unroll
        for (int pt = 0; pt < 2; pt++) {
            const uint32_t row = (uint32_t)(lm_r + (lm_m >> 1) * 8);
            const uint32_t cb  = (uint32_t)((wbase + pt * 16 + (lm_m & 1) * 8) * 2);
            const uint32_t lmoff = swz(row, cb);
            uint32_t ah[4], am[4];
            ldsm4t(ah[0], ah[1], ah[2], ah[3], Asm + lmoff);
            ldsm4t(am[0], am[1], am[2], am[3], Asm + ATILE + lmoff);
            #pragma unroll
            for (int nt = 0; nt < 4; nt++) {
                mma_bf16(d[pt][nt], ah, bh[nt]);
                mma_bf16(d[pt][nt], ah, bm[nt]);
                mma_bf16(d[pt][nt], am, bh[nt]);
            }
        }
    }

    // ---- epilogue: bias + scatter ----
    #pragma unroll
    for (int pt = 0; pt < 2; pt++) {
        const int p0 = wbase + pt * 16 + (lane >> 2);
        const int p1 = p0 + 8;
        const float bv0 = bias[p0 * LL + l];
        const float bv1 = bias[p1 * LL + l];
        const int c0 = p0 >> 2, kh0 = (p0 >> 1) & 1, kw0 = p0 & 1;
        const int c1 = p1 >> 2, kh1 = (p1 >> 1) & 1, kw1 = p1 & 1;
        #pragma unroll
        for (int nt = 0; nt < 4; nt++) {
            const int b = nt * 8 + 2 * (lane & 3);
            const size_t o0 = (size_t)(((b * CC + c0) * HH + 2 * ph + kh0) * HH + 2 * pw + kw0);
            const size_t o1 = (size_t)(((b * CC + c1) * HH + 2 * ph + kh1) * HH + 2 * pw + kw1);
            const size_t bs = (size_t)CC * HH * HH;
            out[o0]      = d[pt][nt][0] + bv0;
            out[o0 + bs] = d[pt][nt][1] + bv0;
            out[o1]      = d[pt][nt][2] + bv1;
            out[o1 + bs] = d[pt][nt][3] + bv1;
        }
    }
}

extern "C" void kernel_launch(void* const* d_in, const int* in_sizes, int n_in,
                              void* d_out, int out_size)
{
    const float* x    = (const float*)d_in[0];
    const float* w    = (const float*)d_in[1];
    const float* bias = (const float*)d_in[2];
    float* out        = (float*)d_out;

    cudaFuncSetAttribute(pointconv_mma,
                         cudaFuncAttributeMaxDynamicSharedMemorySize, SMEM_TOTAL);
    pointconv_mma<<<LL, 256, SMEM_TOTAL>>>(x, w, bias, out);
}